// round 13
// baseline (speedup 1.0000x reference)
#include <cuda_runtime.h>
#include <cstdint>

#define N_TOK   2048
#define IN_F    2048
#define OUT_F   2048
#define OBLK    64
#define IBLK    64
#define NNZ     1228
#define TILE_T  128
#define THREADS 128
#define PIPE    4
#define NGRP    32                         // groups of 2 output blocks

#define XS_STRIDE 36                       // words per token row (144B, conflict-free)
#define XS_WORDS  (TILE_T * XS_STRIDE)     // 4608 words = 18432 B
#define SMEM_BYTES (PIPE * XS_WORDS * 4)   // 73728 B

// w pre-converted to tf32 (RNA), MMA-fragment order (see convert_w_kernel)
__device__ uint32_t g_wtf[NNZ * 1024];
// per-group union of input blocks: count, ib list, and w-block index per row (-1 if absent)
__device__ int g_ucnt[NGRP];
__device__ int g_uib[NGRP * IBLK];
__device__ int g_uka[NGRP * IBLK];
__device__ int g_ukb[NGRP * IBLK];

__global__ void convert_w_kernel(const float* __restrict__ w) {
    const int kb = blockIdx.x;
    const int r  = threadIdx.x;              // 0..255
    const int ks   = r >> 6;
    const int half = (r >> 5) & 1;
    const int lane = r & 31;
    const float* wb = w + (size_t)kb * 1024;
    uint32_t o[4];
#pragma unroll
    for (int m = 0; m < 4; ++m) {
        const int j  = half * 4 + m;
        const int nt = j >> 1, c = j & 1;
        const float v = wb[(nt * 8 + (lane >> 2)) * 32 + ks * 8 + c * 4 + (lane & 3)];
        asm("cvt.rna.tf32.f32 %0, %1;" : "=r"(o[m]) : "f"(v));
    }
    ((uint4*)g_wtf)[(size_t)kb * 256 + r] = make_uint4(o[0], o[1], o[2], o[3]);
}

// Build the union list for each 2-row group. Deterministic (prefix scan, ib order).
__global__ void build_union_kernel(const int* __restrict__ oi, const int* __restrict__ ii) {
    const int g = blockIdx.x;        // 0..NGRP-1
    const int t = threadIdx.x;       // 0..63 = candidate ib
    __shared__ int flags[IBLK], ka_s[IBLK], kb_s[IBLK], pos[IBLK];

    const int r0 = 2 * g;
    // row ranges in the sorted oi array
    int a0, a1, b1;
    {
        int lo = 0, hi = NNZ;
        while (lo < hi) { int m = (lo + hi) >> 1; if (__ldg(oi + m) < r0) lo = m + 1; else hi = m; }
        a0 = lo; hi = NNZ;
        while (lo < hi) { int m = (lo + hi) >> 1; if (__ldg(oi + m) < r0 + 1) lo = m + 1; else hi = m; }
        a1 = lo; hi = NNZ;
        while (lo < hi) { int m = (lo + hi) >> 1; if (__ldg(oi + m) < r0 + 2) lo = m + 1; else hi = m; }
        b1 = lo;
    }
    // membership of ib==t in each row (ii ascending within a row)
    int ka = -1;
    { int lo = a0, hi = a1;
      while (lo < hi) { int m = (lo + hi) >> 1; if (__ldg(ii + m) < t) lo = m + 1; else hi = m; }
      if (lo < a1 && __ldg(ii + lo) == t) ka = lo; }
    int kb = -1;
    { int lo = a1, hi = b1;
      while (lo < hi) { int m = (lo + hi) >> 1; if (__ldg(ii + m) < t) lo = m + 1; else hi = m; }
      if (lo < b1 && __ldg(ii + lo) == t) kb = lo; }

    const int pres = (ka >= 0 || kb >= 0) ? 1 : 0;
    flags[t] = pres; ka_s[t] = ka; kb_s[t] = kb;
    __syncthreads();
    if (t == 0) { int s = 0; for (int i = 0; i < IBLK; ++i) { pos[i] = s; s += flags[i]; } g_ucnt[g] = s; }
    __syncthreads();
    if (pres) {
        const int p = g * IBLK + pos[t];
        g_uib[p] = t; g_uka[p] = ka_s[t]; g_ukb[p] = kb_s[t];
    }
}

// ---------- helpers ----------
__device__ __forceinline__ uint32_t smem_u32(const void* p) {
    uint32_t a;
    asm("{ .reg .u64 t; cvta.to.shared.u64 t, %1; cvt.u32.u64 %0, t; }" : "=r"(a) : "l"(p));
    return a;
}
__device__ __forceinline__ void cp16(uint32_t dst, const void* src) {
    asm volatile("cp.async.cg.shared.global [%0], [%1], 16;" :: "r"(dst), "l"(src) : "memory");
}
__device__ __forceinline__ void cp_commit() { asm volatile("cp.async.commit_group;" ::: "memory"); }
__device__ __forceinline__ void cp_wait2()  { asm volatile("cp.async.wait_group 2;"  ::: "memory"); }

__device__ __forceinline__ void mma_tf32(float& c0, float& c1, float& c2, float& c3,
                                         uint32_t a0, uint32_t a1, uint32_t a2, uint32_t a3,
                                         uint32_t b0, uint32_t b1) {
    asm volatile("mma.sync.aligned.m16n8k8.row.col.f32.tf32.tf32.f32 "
                 "{%0,%1,%2,%3}, {%4,%5,%6,%7}, {%8,%9}, {%0,%1,%2,%3};"
                 : "+f"(c0), "+f"(c1), "+f"(c2), "+f"(c3)
                 : "r"(a0), "r"(a1), "r"(a2), "r"(a3), "r"(b0), "r"(b1));
}

// ---------- main kernel ----------
// CTA = 128 tokens x 2 output blocks; iterates the UNION of the pair's input
// blocks so each x tile is gathered once per pair. Warp-private pipeline
// (producer == consumer per warp), no main-loop barriers.
__global__ __launch_bounds__(THREADS, 3) void bsmm_mma_kernel(
    const float* __restrict__ x,
    float*       __restrict__ y)
{
    extern __shared__ uint32_t xsb[];       // PIPE x-tile buffers (raw f32 bits)

    const int g    = blockIdx.x;            // output-block pair
    const int t0   = blockIdx.y * TILE_T;
    const int tid  = threadIdx.x;
    const int wid  = tid >> 5;              // 0..3, owns 32 token rows
    const int lane = tid & 31;
    const int cq   = lane & 7;              // copy: float4 column
    const int cr   = lane >> 3;             // copy: row-within-4group

    const uint32_t xs_base = smem_u32(xsb);

    const int nblk = g_ucnt[g];
    const int* uib = g_uib + g * IBLK;
    const int* uka = g_uka + g * IBLK;
    const int* ukb = g_ukb + g * IBLK;

    float c[2][2][4][4];                     // [row][mt][nt][reg]
#pragma unroll
    for (int rr = 0; rr < 2; ++rr)
#pragma unroll
        for (int mt = 0; mt < 2; ++mt)
#pragma unroll
            for (int nt = 0; nt < 4; ++nt)
#pragma unroll
                for (int r = 0; r < 4; ++r) c[rr][mt][nt][r] = 0.0f;

    if (nblk > 0) {
        const int wrow0 = wid * 32;

        // -------- prologue: stage this warp's rows of tiles 0..PIPE-2 --------
#pragma unroll
        for (int p = 0; p < PIPE - 1; ++p) {
            if (p < nblk) {
                const int ib = __ldg(uib + p);
                const float* xg = x + (size_t)(t0 + wrow0) * IN_F + (size_t)ib * 32 + cq * 4;
                const uint32_t xd = xs_base +
                    (uint32_t)(p * XS_WORDS + wrow0 * XS_STRIDE + cq * 4) * 4;
#pragma unroll
                for (int it = 0; it < 8; ++it) {
                    const int r = it * 4 + cr;
                    cp16(xd + (uint32_t)(r * XS_STRIDE) * 4, xg + (size_t)r * IN_F);
                }
            }
            cp_commit();
        }

        const int kq  = lane & 3;
        const int rA0 = (wrow0 + (lane >> 2)) * XS_STRIDE + kq;   // mt=0 rows
        const int rA1 = rA0 + 16 * XS_STRIDE;                     // mt=1 rows

        // -------- main loop --------
        for (int j = 0; j < nblk; ++j) {
            const int s = j & (PIPE - 1);
            const int ka = __ldg(uka + j);
            const int kb = __ldg(ukb + j);

            cp_wait2();            // this warp's rows of tile j resident

            const uint32_t* xb = xsb + s * XS_WORDS;
            const uint4* wa = (const uint4*)(g_wtf + (size_t)(ka < 0 ? 0 : ka) * 1024) + lane;
            const uint4* wb = (const uint4*)(g_wtf + (size_t)(kb < 0 ? 0 : kb) * 1024) + lane;

#pragma unroll
            for (int ks = 0; ks < 4; ++ks) {
                const int o = 8 * ks;
                // A fragments: loaded once, shared by both output rows
                const uint32_t a0 = xb[rA0 + o];
                const uint32_t a1 = xb[rA0 + 8 * XS_STRIDE + o];
                const uint32_t a2 = xb[rA0 + o + 4];
                const uint32_t a3 = xb[rA0 + 8 * XS_STRIDE + o + 4];
                const uint32_t a4 = xb[rA1 + o];
                const uint32_t a5 = xb[rA1 + 8 * XS_STRIDE + o];
                const uint32_t a6 = xb[rA1 + o + 4];
                const uint32_t a7 = xb[rA1 + 8 * XS_STRIDE + o + 4];

                if (ka >= 0) {      // uniform across CTA
                    const uint4 b01 = __ldg(wa + ks * 64);
                    const uint4 b23 = __ldg(wa + ks * 64 + 32);
                    mma_tf32(c[0][0][0][0], c[0][0][0][1], c[0][0][0][2], c[0][0][0][3], a0, a1, a2, a3, b01.x, b01.y);
                    mma_tf32(c[0][0][1][0], c[0][0][1][1], c[0][0][1][2], c[0][0][1][3], a0, a1, a2, a3, b01.z, b01.w);
                    mma_tf32(c[0][0][2][0], c[0][0][2][1], c[0][0][2][2], c[0][0][2][3], a0, a1, a2, a3, b23.x, b23.y);
                    mma_tf32(c[0][0][3][0], c[0][0][3][1], c[0][0][3][2], c[0][0][3][3], a0, a1, a2, a3, b23.z, b23.w);
                    mma_tf32(c[0][1][0][0], c[0][1][0][1], c[0][1][0][2], c[0][1][0][3], a4, a5, a6, a7, b01.x, b01.y);
                    mma_tf32(c[0][1][1][0], c[0][1][1][1], c[0][1][1][2], c[0][1][1][3], a4, a5, a6, a7, b01.z, b01.w);
                    mma_tf32(c[0][1][2][0], c[0][1][2][1], c[0][1][2][2], c[0][1][2][3], a4, a5, a6, a7, b23.x, b23.y);
                    mma_tf32(c[0][1][3][0], c[0][1][3][1], c[0][1][3][2], c[0][1][3][3], a4, a5, a6, a7, b23.z, b23.w);
                }
                if (kb >= 0) {
                    const uint4 b01 = __ldg(wb + ks * 64);
                    const uint4 b23 = __ldg(wb + ks * 64 + 32);
                    mma_tf32(c[1][0][0][0], c[1][0][0][1], c[1][0][0][2], c[1][0][0][3], a0, a1, a2, a3, b01.x, b01.y);
                    mma_tf32(c[1][0][1][0], c[1][0][1][1], c[1][0][1][2], c[1][0][1][3], a0, a1, a2, a3, b01.z, b01.w);
                    mma_tf32(c[1][0][2][0], c[1][0][2][1], c[1][0][2][2], c[1][0][2][3], a0, a1, a2, a3, b23.x, b23.y);
                    mma_tf32(c[1][0][3][0], c[1][0][3][1], c[1][0][3][2], c[1][0][3][3], a0, a1, a2, a3, b23.z, b23.w);
                    mma_tf32(c[1][1][0][0], c[1][1][0][1], c[1][1][0][2], c[1][1][0][3], a4, a5, a6, a7, b01.x, b01.y);
                    mma_tf32(c[1][1][1][0], c[1][1][1][1], c[1][1][1][2], c[1][1][1][3], a4, a5, a6, a7, b01.z, b01.w);
                    mma_tf32(c[1][1][2][0], c[1][1][2][1], c[1][1][2][2], c[1][1][2][3], a4, a5, a6, a7, b23.x, b23.y);
                    mma_tf32(c[1][1][3][0], c[1][1][3][1], c[1][1][3][2], c[1][1][3][3], a4, a5, a6, a7, b23.z, b23.w);
                }
            }

            // ---- prefetch this warp's rows of tile j+PIPE-1 (WAR-safe) ----
            if (j + PIPE - 1 < nblk) {
                const int ib = __ldg(uib + j + PIPE - 1);
                const float* xg = x + (size_t)(t0 + wrow0) * IN_F + (size_t)ib * 32 + cq * 4;
                const uint32_t xd = xs_base +
                    (uint32_t)(((j + PIPE - 1) & (PIPE - 1)) * XS_WORDS +
                               wrow0 * XS_STRIDE + cq * 4) * 4;
#pragma unroll
                for (int it = 0; it < 8; ++it) {
                    const int r = it * 4 + cr;
                    cp16(xd + (uint32_t)(r * XS_STRIDE) * 4, xg + (size_t)r * IN_F);
                }
            }
            cp_commit();           // unconditional: exact group accounting
        }
    }

    // -------- epilogue: both rows (zeros where no nnz) --------
#pragma unroll
    for (int rr = 0; rr < 2; ++rr) {
        const int ob = 2 * g + rr;
#pragma unroll
        for (int mt = 0; mt < 2; ++mt) {
#pragma unroll
            for (int nt = 0; nt < 4; ++nt) {
                const int row = t0 + wid * 32 + mt * 16 + (lane >> 2);
                const int col = ob * 32 + nt * 8 + (lane & 3) * 2;
                *(float2*)(y + (size_t)row * OUT_F + col)       = make_float2(c[rr][mt][nt][0], c[rr][mt][nt][1]);
                *(float2*)(y + (size_t)(row + 8) * OUT_F + col) = make_float2(c[rr][mt][nt][2], c[rr][mt][nt][3]);
            }
        }
    }
}

extern "C" void kernel_launch(void* const* d_in, const int* in_sizes, int n_in,
                              void* d_out, int out_size) {
    const float* x  = (const float*)d_in[0];
    const float* w  = (const float*)d_in[1];
    const int*   oi = (const int*)  d_in[2];
    const int*   ii = (const int*)  d_in[3];
    float*       y  = (float*)d_out;

    static int smem_set = 0;
    if (!smem_set) {
        cudaFuncSetAttribute(bsmm_mma_kernel,
                             cudaFuncAttributeMaxDynamicSharedMemorySize, SMEM_BYTES);
        smem_set = 1;
    }

    convert_w_kernel<<<NNZ, 256>>>(w);
    build_union_kernel<<<NGRP, IBLK>>>(oi, ii);

    dim3 grid(NGRP, N_TOK / TILE_T);
    bsmm_mma_kernel<<<grid, THREADS, SMEM_BYTES>>>(x, y);
}

// round 14
// speedup vs baseline: 1.4887x; 1.4887x over previous
#include <cuda_runtime.h>
#include <cstdint>

#define N_TOK   2048
#define IN_F    2048
#define OUT_F   2048
#define OBLK    64
#define NNZ     1228
#define TILE_T  128
#define THREADS 128
#define PIPE    3

#define XS_STRIDE 36                       // words per token row (144B, conflict-free)
#define XS_WORDS  (TILE_T * XS_STRIDE)     // 4608 words = 18432 B
#define SMEM_BYTES (PIPE * XS_WORDS * 4)   // 55296 B -> occ 4

// w pre-converted to tf32 (RNA), MMA-fragment order:
// word index = kb*1024 + ks*256 + half*128 + lane*4 + m
//   (half*4+m) -> nt = j>>1, c = j&1
//   value = tf32( w[kb][ o = nt*8 + (lane>>2) ][ i = ks*8 + c*4 + (lane&3) ] )
__device__ uint32_t g_wtf[NNZ * 1024];

__global__ void convert_w_kernel(const float* __restrict__ w) {
    const int kb = blockIdx.x;
    const int r  = threadIdx.x;              // 0..255
    const int ks   = r >> 6;
    const int half = (r >> 5) & 1;
    const int lane = r & 31;
    const float* wb = w + (size_t)kb * 1024;
    uint32_t o[4];
#pragma unroll
    for (int m = 0; m < 4; ++m) {
        const int j  = half * 4 + m;
        const int nt = j >> 1, c = j & 1;
        const float v = wb[(nt * 8 + (lane >> 2)) * 32 + ks * 8 + c * 4 + (lane & 3)];
        asm("cvt.rna.tf32.f32 %0, %1;" : "=r"(o[m]) : "f"(v));
    }
    ((uint4*)g_wtf)[(size_t)kb * 256 + r] = make_uint4(o[0], o[1], o[2], o[3]);
}

// ---------- helpers ----------
__device__ __forceinline__ uint32_t smem_u32(const void* p) {
    uint32_t a;
    asm("{ .reg .u64 t; cvta.to.shared.u64 t, %1; cvt.u32.u64 %0, t; }" : "=r"(a) : "l"(p));
    return a;
}
__device__ __forceinline__ void cp16(uint32_t dst, const void* src) {
    asm volatile("cp.async.cg.shared.global [%0], [%1], 16;" :: "r"(dst), "l"(src) : "memory");
}
__device__ __forceinline__ void cp_commit() { asm volatile("cp.async.commit_group;" ::: "memory"); }
__device__ __forceinline__ void cp_wait1()  { asm volatile("cp.async.wait_group 1;"  ::: "memory"); }

__device__ __forceinline__ void mma_tf32(float& c0, float& c1, float& c2, float& c3,
                                         uint32_t a0, uint32_t a1, uint32_t a2, uint32_t a3,
                                         uint32_t b0, uint32_t b1) {
    asm volatile("mma.sync.aligned.m16n8k8.row.col.f32.tf32.tf32.f32 "
                 "{%0,%1,%2,%3}, {%4,%5,%6,%7}, {%8,%9}, {%0,%1,%2,%3};"
                 : "+f"(c0), "+f"(c1), "+f"(c2), "+f"(c3)
                 : "r"(a0), "r"(a1), "r"(a2), "r"(a3), "r"(b0), "r"(b1));
}

// ---------- main kernel ----------
// Warp-private pipeline: warp wid copies AND consumes rows [wid*32, wid*32+32)
// of each x tile. No __syncthreads in the main loop; PIPE=3 buffers -> occ 4.
__global__ __launch_bounds__(THREADS, 4) void bsmm_mma_kernel(
    const float* __restrict__ x,
    const int*   __restrict__ oi,
    const int*   __restrict__ ii,
    float*       __restrict__ y)
{
    extern __shared__ uint32_t xsb[];       // PIPE x-tile buffers (raw f32 bits)

    const int ob   = blockIdx.x;
    const int t0   = blockIdx.y * TILE_T;
    const int tid  = threadIdx.x;
    const int wid  = tid >> 5;              // 0..3, owns 32 token rows
    const int lane = tid & 31;
    const int cq   = lane & 7;              // copy: float4 column (0..7)
    const int cr   = lane >> 3;             // copy: row-within-4group (0..3)

    const uint32_t xs_base = smem_u32(xsb);

    // CSR bounds via binary search on sorted oi
    int k0, k1;
    {
        int lo = 0, hi = NNZ;
        while (lo < hi) { int m = (lo + hi) >> 1; if (__ldg(oi + m) < ob) lo = m + 1; else hi = m; }
        k0 = lo; hi = NNZ;
        while (lo < hi) { int m = (lo + hi) >> 1; if (__ldg(oi + m) < ob + 1) lo = m + 1; else hi = m; }
        k1 = lo;
    }
    const int nblk = k1 - k0;

    float c[2][4][4];
#pragma unroll
    for (int mt = 0; mt < 2; ++mt)
#pragma unroll
        for (int nt = 0; nt < 4; ++nt)
#pragma unroll
            for (int r = 0; r < 4; ++r) c[mt][nt][r] = 0.0f;

    if (nblk > 0) {
        const int wrow0 = wid * 32;         // warp's first token row in the tile

        // -------- prologue: stage this warp's rows of tiles 0..PIPE-2 --------
#pragma unroll
        for (int p = 0; p < PIPE - 1; ++p) {
            if (p < nblk) {
                const int ib = __ldg(ii + k0 + p);
                const float* xg = x + (size_t)(t0 + wrow0) * IN_F + (size_t)ib * 32 + cq * 4;
                const uint32_t xd = xs_base +
                    (uint32_t)(p * XS_WORDS + wrow0 * XS_STRIDE + cq * 4) * 4;
#pragma unroll
                for (int it = 0; it < 8; ++it) {
                    const int r = it * 4 + cr;
                    cp16(xd + (uint32_t)(r * XS_STRIDE) * 4, xg + (size_t)r * IN_F);
                }
            }
            cp_commit();
        }

        const int kq   = lane & 3;
        const int rA0  = (wrow0 + (lane >> 2)) * XS_STRIDE + kq;   // mt=0 rows
        const int rA1  = rA0 + 16 * XS_STRIDE;                     // mt=1 rows

        int s  = 0;                         // consume slot
        int sp = PIPE - 1;                  // prefetch slot (j + PIPE-1)

        // -------- main loop (no barriers: producer == consumer per warp) ----
        for (int j = 0; j < nblk; ++j) {
            cp_wait1();            // this warp's rows of tile j resident

            const uint32_t* xb  = xsb + s * XS_WORDS;
            const uint4*    wkb = (const uint4*)(g_wtf + (size_t)(k0 + j) * 1024) + lane;

#pragma unroll
            for (int ks = 0; ks < 4; ++ks) {
                // B fragments: 2 coalesced LDG.128 (L1-resident), interleaved per ks
                const uint4 b01 = __ldg(wkb + ks * 64);        // nt0, nt1
                const uint4 b23 = __ldg(wkb + ks * 64 + 32);   // nt2, nt3
                const int o = 8 * ks;
                // mt = 0  (raw f32 bits; tf32 MMA ignores low mantissa bits)
                {
                    const uint32_t a0 = xb[rA0 + o];
                    const uint32_t a1 = xb[rA0 + 8 * XS_STRIDE + o];
                    const uint32_t a2 = xb[rA0 + o + 4];
                    const uint32_t a3 = xb[rA0 + 8 * XS_STRIDE + o + 4];
                    mma_tf32(c[0][0][0], c[0][0][1], c[0][0][2], c[0][0][3], a0, a1, a2, a3, b01.x, b01.y);
                    mma_tf32(c[0][1][0], c[0][1][1], c[0][1][2], c[0][1][3], a0, a1, a2, a3, b01.z, b01.w);
                    mma_tf32(c[0][2][0], c[0][2][1], c[0][2][2], c[0][2][3], a0, a1, a2, a3, b23.x, b23.y);
                    mma_tf32(c[0][3][0], c[0][3][1], c[0][3][2], c[0][3][3], a0, a1, a2, a3, b23.z, b23.w);
                }
                // mt = 1
                {
                    const uint32_t a0 = xb[rA1 + o];
                    const uint32_t a1 = xb[rA1 + 8 * XS_STRIDE + o];
                    const uint32_t a2 = xb[rA1 + o + 4];
                    const uint32_t a3 = xb[rA1 + 8 * XS_STRIDE + o + 4];
                    mma_tf32(c[1][0][0], c[1][0][1], c[1][0][2], c[1][0][3], a0, a1, a2, a3, b01.x, b01.y);
                    mma_tf32(c[1][1][0], c[1][1][1], c[1][1][2], c[1][1][3], a0, a1, a2, a3, b01.z, b01.w);
                    mma_tf32(c[1][2][0], c[1][2][1], c[1][2][2], c[1][2][3], a0, a1, a2, a3, b23.x, b23.y);
                    mma_tf32(c[1][3][0], c[1][3][1], c[1][3][2], c[1][3][3], a0, a1, a2, a3, b23.z, b23.w);
                }
            }

            // ---- prefetch this warp's rows of tile j+PIPE-1 (after consume:
            //      slot last read at iter j-1, WAR-safe) ----
            if (j + PIPE - 1 < nblk) {
                const int ib = __ldg(ii + k0 + j + PIPE - 1);
                const float* xg = x + (size_t)(t0 + wrow0) * IN_F + (size_t)ib * 32 + cq * 4;
                const uint32_t xd = xs_base +
                    (uint32_t)(sp * XS_WORDS + wrow0 * XS_STRIDE + cq * 4) * 4;
#pragma unroll
                for (int it = 0; it < 8; ++it) {
                    const int r = it * 4 + cr;
                    cp16(xd + (uint32_t)(r * XS_STRIDE) * 4, xg + (size_t)r * IN_F);
                }
            }
            cp_commit();           // unconditional: exact group accounting

            if (++s == PIPE) s = 0;
            if (++sp == PIPE) sp = 0;
        }
    }

    // -------- epilogue (also writes zeros for empty output blocks) --------
#pragma unroll
    for (int mt = 0; mt < 2; ++mt) {
#pragma unroll
        for (int nt = 0; nt < 4; ++nt) {
            const int row = t0 + wid * 32 + mt * 16 + (lane >> 2);
            const int col = ob * 32 + nt * 8 + (lane & 3) * 2;
            *(float2*)(y + (size_t)row * OUT_F + col)       = make_float2(c[mt][nt][0], c[mt][nt][1]);
            *(float2*)(y + (size_t)(row + 8) * OUT_F + col) = make_float2(c[mt][nt][2], c[mt][nt][3]);
        }
    }
}

extern "C" void kernel_launch(void* const* d_in, const int* in_sizes, int n_in,
                              void* d_out, int out_size) {
    const float* x  = (const float*)d_in[0];
    const float* w  = (const float*)d_in[1];
    const int*   oi = (const int*)  d_in[2];
    const int*   ii = (const int*)  d_in[3];
    float*       y  = (float*)d_out;

    static int smem_set = 0;
    if (!smem_set) {
        cudaFuncSetAttribute(bsmm_mma_kernel,
                             cudaFuncAttributeMaxDynamicSharedMemorySize, SMEM_BYTES);
        smem_set = 1;
    }

    convert_w_kernel<<<NNZ, 256>>>(w);

    dim3 grid(OBLK, N_TOK / TILE_T);
    bsmm_mma_kernel<<<grid, THREADS, SMEM_BYTES>>>(x, oi, ii, y);
}